// round 1
// baseline (speedup 1.0000x reference)
#include <cuda_runtime.h>

#define NT    8192
#define KT    200
#define CINC  512
#define HIDC  256
#define COUTC 40
#define EE    5
#define MHD   64
#define TGRID 16384
#define TBL_LO (-8.0f)
#define TBL_HI ( 8.0f)

// ---------------- scratch (device globals; no runtime alloc) ----------------
__device__ float d_ftable[EE * TGRID];
__device__ float d_V[KT];
__device__ float d_s[KT];
__device__ float d_Tm[KT * CINC];        // U^T X   [200 x 512]
__device__ float d_Y[NT * CINC];         // (U*s) @ T  [8192 x 512]
__device__ float d_colsum[HIDC], d_colsq[HIDC], d_mu[HIDC], d_rsig[HIDC];

// ---------------- zero the atomic accumulators ----------------
__global__ void k_zero() {
    int i = blockIdx.x * blockDim.x + threadIdx.x;
    if (i < KT * CINC) d_Tm[i] = 0.f;
    if (i < HIDC) { d_colsum[i] = 0.f; d_colsq[i] = 0.f; }
}

// ---------------- build per-expert PWL tables ----------------
__global__ void k_table(const float* __restrict__ eW1, const float* __restrict__ eb1,
                        const float* __restrict__ eW2, const float* __restrict__ eb2,
                        const float* __restrict__ eW3, const float* __restrict__ eb3) {
    int e = blockIdx.y;
    __shared__ float W2s[MHD * MHD];
    __shared__ float W1s[MHD], b1s[MHD], b2s[MHD], W3s[MHD];
    for (int i = threadIdx.x; i < MHD * MHD; i += blockDim.x) W2s[i] = eW2[e * MHD * MHD + i];
    if (threadIdx.x < MHD) {
        W1s[threadIdx.x] = eW1[e * MHD + threadIdx.x];
        b1s[threadIdx.x] = eb1[e * MHD + threadIdx.x];
        b2s[threadIdx.x] = eb2[e * MHD + threadIdx.x];
        W3s[threadIdx.x] = eW3[e * MHD + threadIdx.x];
    }
    __syncthreads();

    int t = blockIdx.x * blockDim.x + threadIdx.x;
    float x = TBL_LO + (TBL_HI - TBL_LO) * ((float)t / (float)(TGRID - 1));

    float h1[MHD];
#pragma unroll
    for (int h = 0; h < MHD; h++) h1[h] = fmaxf(fmaf(x, W1s[h], b1s[h]), 0.f);

    float v = eb3[e];
    for (int j = 0; j < MHD; j += 2) {
        float a0 = b2s[j], a1 = b2s[j + 1];
#pragma unroll
        for (int h = 0; h < MHD; h++) {
            float hv = h1[h];
            a0 = fmaf(hv, W2s[h * MHD + j],     a0);
            a1 = fmaf(hv, W2s[h * MHD + j + 1], a1);
        }
        v = fmaf(fmaxf(a0, 0.f), W3s[j],     v);
        v = fmaf(fmaxf(a1, 0.f), W3s[j + 1], v);
    }
    d_ftable[e * TGRID + t] = v;
}

// ---------------- V[col] = mean_n lerp(f_e, U[n,col]) ----------------
__global__ void k_reduceV(const float* __restrict__ U) {
    int col = blockIdx.x;
    int e = col / 40;
    const float* tbl = d_ftable + e * TGRID;
    const float scale = (float)(TGRID - 1) / (TBL_HI - TBL_LO);

    float sum = 0.f;
    for (int n = threadIdx.x; n < NT; n += 256) {
        float u  = U[n * KT + col];
        float xi = (u - TBL_LO) * scale;
        xi = fminf(fmaxf(xi, 0.f), (float)(TGRID - 2) + 0.9999f);
        int   i  = (int)xi;
        float fr = xi - (float)i;
        float a = tbl[i], b = tbl[i + 1];
        sum += fmaf(fr, b - a, a);
    }
    __shared__ float red[256];
    red[threadIdx.x] = sum;
    __syncthreads();
    for (int off = 128; off; off >>= 1) {
        if (threadIdx.x < off) red[threadIdx.x] += red[threadIdx.x + off];
        __syncthreads();
    }
    if (threadIdx.x == 0) d_V[col] = red[0] * (1.f / (float)NT);
}

// ---------------- gate (5x5 MLP + softmax) and s[k] = g[e]*V[k] ----------------
__global__ void k_gate(const float* __restrict__ La,
                       const float* __restrict__ gW1, const float* __restrict__ gb1,
                       const float* __restrict__ gW2, const float* __restrict__ gb2) {
    __shared__ float stats[EE], gsh[EE];
    int tid = threadIdx.x;
    if (tid < EE) {
        float s = 0.f;
        for (int i = 0; i < 40; i++) s += La[tid * 40 + i];
        stats[tid] = s * (1.f / 40.f);
    }
    __syncthreads();
    if (tid == 0) {
        float h[EE], g2[EE];
        for (int j = 0; j < EE; j++) {
            float a = gb1[j];
            for (int i = 0; i < EE; i++) a = fmaf(stats[i], gW1[i * EE + j], a);
            h[j] = fmaxf(a, 0.f);
        }
        for (int j = 0; j < EE; j++) {
            float a = gb2[j];
            for (int i = 0; i < EE; i++) a = fmaf(h[i], gW2[i * EE + j], a);
            g2[j] = a;
        }
        float m = g2[0];
        for (int j = 1; j < EE; j++) m = fmaxf(m, g2[j]);
        float se = 0.f;
        for (int j = 0; j < EE; j++) { g2[j] = expf(g2[j] - m); se += g2[j]; }
        for (int j = 0; j < EE; j++) gsh[j] = g2[j] / se;
    }
    __syncthreads();
    if (tid < KT) d_s[tid] = gsh[tid / 40] * d_V[tid];
}

// ---------------- T = U^T @ X  [200 x 512], split over N with atomics ----------------
__global__ void __launch_bounds__(128) k_gemmT(const float* __restrict__ U,
                                               const float* __restrict__ X) {
    __shared__ float Us[64][8];
    __shared__ float Xs[64][128];
    int cb = blockIdx.x * 128;
    int kb = blockIdx.y * 8;
    int nb = blockIdx.z * 1024;
    int tid = threadIdx.x;
    int tk = tid >> 5, tc = tid & 31;
    int k0 = tk * 2, c0 = tc * 4;
    float acc[2][4] = {};

    for (int nc = 0; nc < 1024; nc += 64) {
#pragma unroll
        for (int l = 0; l < 4; l++) {
            int idx = tid + 128 * l;
            Us[idx >> 3][idx & 7] = U[(nb + nc + (idx >> 3)) * KT + kb + (idx & 7)];
        }
#pragma unroll
        for (int l = 0; l < 16; l++) {
            int idx = tid + 128 * l;
            int nl = idx >> 5, c4 = idx & 31;
            *(float4*)&Xs[nl][c4 * 4] = *(const float4*)&X[(nb + nc + nl) * CINC + cb + c4 * 4];
        }
        __syncthreads();
#pragma unroll 8
        for (int nn = 0; nn < 64; nn++) {
            float u0 = Us[nn][k0], u1 = Us[nn][k0 + 1];
            float4 xv = *(float4*)&Xs[nn][c0];
            acc[0][0] = fmaf(u0, xv.x, acc[0][0]);
            acc[0][1] = fmaf(u0, xv.y, acc[0][1]);
            acc[0][2] = fmaf(u0, xv.z, acc[0][2]);
            acc[0][3] = fmaf(u0, xv.w, acc[0][3]);
            acc[1][0] = fmaf(u1, xv.x, acc[1][0]);
            acc[1][1] = fmaf(u1, xv.y, acc[1][1]);
            acc[1][2] = fmaf(u1, xv.z, acc[1][2]);
            acc[1][3] = fmaf(u1, xv.w, acc[1][3]);
        }
        __syncthreads();
    }
#pragma unroll
    for (int i = 0; i < 2; i++)
#pragma unroll
        for (int j = 0; j < 4; j++)
            atomicAdd(&d_Tm[(kb + k0 + i) * CINC + cb + c0 + j], acc[i][j]);
}

// ---------------- Y = (U * s) @ T  [8192 x 512] ----------------
__global__ void __launch_bounds__(256) k_gemmY(const float* __restrict__ U) {
    __shared__ float Ut[8][68];
    __shared__ float Ts[8][64];
    int cb = blockIdx.x * 64, mb = blockIdx.y * 64;
    int tid = threadIdx.x;
    int tm = tid >> 4, tc = tid & 15;
    float acc[4][4] = {};

    for (int kb = 0; kb < KT; kb += 8) {
#pragma unroll
        for (int l = 0; l < 2; l++) {
            int idx = tid + 256 * l;
            Ut[idx & 7][idx >> 3] = U[(mb + (idx >> 3)) * KT + kb + (idx & 7)];
            int kk = idx >> 6, c = idx & 63;
            Ts[kk][c] = d_s[kb + kk] * d_Tm[(kb + kk) * CINC + cb + c];
        }
        __syncthreads();
#pragma unroll
        for (int kk = 0; kk < 8; kk++) {
            float4 um = *(float4*)&Ut[kk][tm * 4];
            float4 tv = *(float4*)&Ts[kk][tc * 4];
            float a[4] = {um.x, um.y, um.z, um.w};
            float b[4] = {tv.x, tv.y, tv.z, tv.w};
#pragma unroll
            for (int i = 0; i < 4; i++)
#pragma unroll
                for (int j = 0; j < 4; j++)
                    acc[i][j] = fmaf(a[i], b[j], acc[i][j]);
        }
        __syncthreads();
    }
#pragma unroll
    for (int i = 0; i < 4; i++)
#pragma unroll
        for (int j = 0; j < 4; j++)
            d_Y[(mb + tm * 4 + i) * CINC + cb + tc * 4 + j] = acc[i][j];
}

// ---------------- hidden = Y @ Ww + Wb  [8192 x 256] ----------------
__global__ void __launch_bounds__(256) k_gemmH(const float* __restrict__ Ww,
                                               const float* __restrict__ Wb,
                                               float* __restrict__ hid) {
    __shared__ float Yt[16][68];
    __shared__ float Ws[16][64];
    int cb = blockIdx.x * 64, mb = blockIdx.y * 64;
    int tid = threadIdx.x;
    int tm = tid >> 4, tc = tid & 15;
    float acc[4][4] = {};

    for (int kb = 0; kb < CINC; kb += 16) {
#pragma unroll
        for (int l = 0; l < 4; l++) {
            int idx = tid + 256 * l;
            Yt[idx & 15][idx >> 4] = d_Y[(mb + (idx >> 4)) * CINC + kb + (idx & 15)];
            int kk = idx >> 6, c = idx & 63;
            Ws[kk][c] = Ww[(kb + kk) * HIDC + cb + c];
        }
        __syncthreads();
#pragma unroll
        for (int kk = 0; kk < 16; kk++) {
            float4 ym = *(float4*)&Yt[kk][tm * 4];
            float4 wv = *(float4*)&Ws[kk][tc * 4];
            float a[4] = {ym.x, ym.y, ym.z, ym.w};
            float b[4] = {wv.x, wv.y, wv.z, wv.w};
#pragma unroll
            for (int i = 0; i < 4; i++)
#pragma unroll
                for (int j = 0; j < 4; j++)
                    acc[i][j] = fmaf(a[i], b[j], acc[i][j]);
        }
        __syncthreads();
    }
#pragma unroll
    for (int i = 0; i < 4; i++)
#pragma unroll
        for (int j = 0; j < 4; j++) {
            int c = cb + tc * 4 + j;
            hid[(mb + tm * 4 + i) * HIDC + c] = acc[i][j] + Wb[c];
        }
}

// ---------------- BN stats ----------------
__global__ void k_bnstats(const float* __restrict__ hid) {
    int c = threadIdx.x;
    int base = blockIdx.x * 32;
    float s = 0.f, q = 0.f;
#pragma unroll 8
    for (int r = 0; r < 32; r++) {
        float v = hid[(base + r) * HIDC + c];
        s += v;
        q = fmaf(v, v, q);
    }
    atomicAdd(&d_colsum[c], s);
    atomicAdd(&d_colsq[c], q);
}

__global__ void k_bnfinal() {
    int c = threadIdx.x;
    float m = d_colsum[c] * (1.f / (float)NT);
    float var = d_colsq[c] * (1.f / (float)NT) - m * m;
    d_mu[c] = m;
    d_rsig[c] = rsqrtf(var + 1e-5f);
}

// ---------------- BN-apply + relu + logits + log_softmax ----------------
__global__ void k_head(const float* __restrict__ hid,
                       const float* __restrict__ gamma, const float* __restrict__ beta,
                       const float* __restrict__ Mw, const float* __restrict__ Mb,
                       float* __restrict__ out) {
    __shared__ float hs[HIDC];
    __shared__ float lg[COUTC];
    __shared__ float red[2];
    int n = blockIdx.x;
    for (int c = threadIdx.x; c < HIDC; c += 64) {
        float v = hid[n * HIDC + c];
        v = fmaf((v - d_mu[c]) * d_rsig[c], gamma[c], beta[c]);
        hs[c] = fmaxf(v, 0.f);
    }
    __syncthreads();
    if (threadIdx.x < COUTC) {
        int j = threadIdx.x;
        float a = Mb[j];
#pragma unroll 8
        for (int c = 0; c < HIDC; c++) a = fmaf(hs[c], Mw[c * COUTC + j], a);
        lg[j] = a;
    }
    __syncthreads();
    if (threadIdx.x == 0) {
        float m = lg[0];
        for (int j = 1; j < COUTC; j++) m = fmaxf(m, lg[j]);
        float se = 0.f;
        for (int j = 0; j < COUTC; j++) se += expf(lg[j] - m);
        red[0] = m;
        red[1] = logf(se);
    }
    __syncthreads();
    if (threadIdx.x < COUTC)
        out[n * COUTC + threadIdx.x] = lg[threadIdx.x] - red[0] - red[1];
}

// ---------------- launch ----------------
extern "C" void kernel_launch(void* const* d_in, const int* in_sizes, int n_in,
                              void* d_out, int out_size) {
    const float* X     = (const float*)d_in[0];
    const float* La    = (const float*)d_in[1];
    const float* U     = (const float*)d_in[2];
    const float* eW1   = (const float*)d_in[3];
    const float* eb1   = (const float*)d_in[4];
    const float* eW2   = (const float*)d_in[5];
    const float* eb2   = (const float*)d_in[6];
    const float* eW3   = (const float*)d_in[7];
    const float* eb3   = (const float*)d_in[8];
    const float* gW1   = (const float*)d_in[9];
    const float* gb1   = (const float*)d_in[10];
    const float* gW2   = (const float*)d_in[11];
    const float* gb2   = (const float*)d_in[12];
    const float* Ww    = (const float*)d_in[13];
    const float* Wb    = (const float*)d_in[14];
    const float* gamma = (const float*)d_in[15];
    const float* beta  = (const float*)d_in[16];
    const float* Mw    = (const float*)d_in[17];
    const float* Mb    = (const float*)d_in[18];

    float* out_logits = (float*)d_out;
    float* out_hidden = (float*)d_out + (size_t)NT * COUTC;

    k_zero<<<(KT * CINC + 255) / 256, 256>>>();
    k_table<<<dim3(TGRID / 128, EE), 128>>>(eW1, eb1, eW2, eb2, eW3, eb3);
    k_reduceV<<<KT, 256>>>(U);
    k_gate<<<1, 256>>>(La, gW1, gb1, gW2, gb2);
    k_gemmT<<<dim3(CINC / 128, KT / 8, 8), 128>>>(U, X);
    k_gemmY<<<dim3(CINC / 64, NT / 64), 256>>>(U);
    k_gemmH<<<dim3(HIDC / 64, NT / 64), 256>>>(Ww, Wb, out_hidden);
    k_bnstats<<<NT / 32, 256>>>(out_hidden);
    k_bnfinal<<<1, HIDC>>>();
    k_head<<<NT, 64>>>(out_hidden, gamma, beta, Mw, Mb, out_logits);
}

// round 2
// speedup vs baseline: 1.9365x; 1.9365x over previous
#include <cuda_runtime.h>

#define NT    8192
#define KT    200
#define CINC  512
#define HIDC  256
#define COUTC 40
#define EE    5
#define MHD   64
#define TGRID 8192
#define TBL_LO (-8.0f)
#define TBL_HI ( 8.0f)
#define PITCH 136

// ---------------- scratch ----------------
__device__ float d_ftable[EE * TGRID];
__device__ float d_Vsum[KT];
__device__ float d_s[KT];
__device__ float d_Tm[KT * CINC];       // T = U^T X   [200 x 512]
__device__ float d_P[KT * HIDC];        // P = T @ Ww  [200 x 256]
__device__ float d_colsum[HIDC], d_colsq[HIDC], d_mu[HIDC], d_rsig[HIDC];

__device__ __forceinline__ unsigned f2tf32(float x) {
    unsigned r;
    asm("cvt.rna.tf32.f32 %0, %1;" : "=r"(r) : "f"(x));
    return r;
}

__device__ __forceinline__ void mma_tf32(float* c, const unsigned* a, const unsigned* b) {
    asm volatile(
        "mma.sync.aligned.m16n8k8.row.col.f32.tf32.tf32.f32 "
        "{%0,%1,%2,%3},{%4,%5,%6,%7},{%8,%9},{%0,%1,%2,%3};"
        : "+f"(c[0]), "+f"(c[1]), "+f"(c[2]), "+f"(c[3])
        : "r"(a[0]), "r"(a[1]), "r"(a[2]), "r"(a[3]), "r"(b[0]), "r"(b[1]));
}

// ---------------- zero accumulators ----------------
__global__ void k_zero() {
    int i = blockIdx.x * blockDim.x + threadIdx.x;
    if (i < KT * CINC) d_Tm[i] = 0.f;
    if (i < KT * HIDC) d_P[i] = 0.f;
    if (i < KT) d_Vsum[i] = 0.f;
    if (i < HIDC) { d_colsum[i] = 0.f; d_colsq[i] = 0.f; }
}

// ---------------- per-expert PWL tables ----------------
__global__ void k_table(const float* __restrict__ eW1, const float* __restrict__ eb1,
                        const float* __restrict__ eW2, const float* __restrict__ eb2,
                        const float* __restrict__ eW3, const float* __restrict__ eb3) {
    int e = blockIdx.y;
    __shared__ float W2s[MHD * MHD];
    __shared__ float W1s[MHD], b1s[MHD], b2s[MHD], W3s[MHD];
    for (int i = threadIdx.x; i < MHD * MHD; i += blockDim.x) W2s[i] = eW2[e * MHD * MHD + i];
    if (threadIdx.x < MHD) {
        W1s[threadIdx.x] = eW1[e * MHD + threadIdx.x];
        b1s[threadIdx.x] = eb1[e * MHD + threadIdx.x];
        b2s[threadIdx.x] = eb2[e * MHD + threadIdx.x];
        W3s[threadIdx.x] = eW3[e * MHD + threadIdx.x];
    }
    __syncthreads();

    int t = blockIdx.x * blockDim.x + threadIdx.x;
    float x = TBL_LO + (TBL_HI - TBL_LO) * ((float)t / (float)(TGRID - 1));

    float h1[MHD];
#pragma unroll
    for (int h = 0; h < MHD; h++) h1[h] = fmaxf(fmaf(x, W1s[h], b1s[h]), 0.f);

    float v = eb3[e];
    for (int j = 0; j < MHD; j += 4) {
        float a0 = b2s[j], a1 = b2s[j + 1], a2 = b2s[j + 2], a3 = b2s[j + 3];
#pragma unroll
        for (int h = 0; h < MHD; h++) {
            float hv = h1[h];
            float4 w = *(const float4*)&W2s[h * MHD + j];
            a0 = fmaf(hv, w.x, a0);
            a1 = fmaf(hv, w.y, a1);
            a2 = fmaf(hv, w.z, a2);
            a3 = fmaf(hv, w.w, a3);
        }
        v = fmaf(fmaxf(a0, 0.f), W3s[j],     v);
        v = fmaf(fmaxf(a1, 0.f), W3s[j + 1], v);
        v = fmaf(fmaxf(a2, 0.f), W3s[j + 2], v);
        v = fmaf(fmaxf(a3, 0.f), W3s[j + 3], v);
    }
    d_ftable[e * TGRID + t] = v;
}

// ---------------- Vsum[col] = sum_n lerp(f_e, U[n,col]) (coalesced) ----------------
__global__ void k_reduceV(const float* __restrict__ U) {
    int col = threadIdx.x;
    if (col >= KT) return;
    int e = col / 40;
    const float* tbl = d_ftable + e * TGRID;
    const float scale = (float)(TGRID - 1) / (TBL_HI - TBL_LO);
    int n0 = blockIdx.x * 128;

    float sum = 0.f;
    for (int n = n0; n < n0 + 128; n++) {
        float u  = U[n * KT + col];
        float xi = (u - TBL_LO) * scale;
        xi = fminf(fmaxf(xi, 0.f), (float)(TGRID - 2) + 0.9999f);
        int   i  = (int)xi;
        float fr = xi - (float)i;
        float a = tbl[i], b = tbl[i + 1];
        sum += fmaf(fr, b - a, a);
    }
    atomicAdd(&d_Vsum[col], sum);
}

// ---------------- gate + s ----------------
__global__ void k_gate(const float* __restrict__ La,
                       const float* __restrict__ gW1, const float* __restrict__ gb1,
                       const float* __restrict__ gW2, const float* __restrict__ gb2) {
    __shared__ float stats[EE], gsh[EE];
    int tid = threadIdx.x;
    if (tid < EE) {
        float s = 0.f;
        for (int i = 0; i < 40; i++) s += La[tid * 40 + i];
        stats[tid] = s * (1.f / 40.f);
    }
    __syncthreads();
    if (tid == 0) {
        float h[EE], g2[EE];
        for (int j = 0; j < EE; j++) {
            float a = gb1[j];
            for (int i = 0; i < EE; i++) a = fmaf(stats[i], gW1[i * EE + j], a);
            h[j] = fmaxf(a, 0.f);
        }
        for (int j = 0; j < EE; j++) {
            float a = gb2[j];
            for (int i = 0; i < EE; i++) a = fmaf(h[i], gW2[i * EE + j], a);
            g2[j] = a;
        }
        float m = g2[0];
        for (int j = 1; j < EE; j++) m = fmaxf(m, g2[j]);
        float se = 0.f;
        for (int j = 0; j < EE; j++) { g2[j] = expf(g2[j] - m); se += g2[j]; }
        for (int j = 0; j < EE; j++) gsh[j] = g2[j] / se;
    }
    __syncthreads();
    if (tid < KT) d_s[tid] = gsh[tid / 40] * d_Vsum[tid] * (1.f / (float)NT);
}

// ============ 3xtf32 GEMM: T = U^T @ X  [200 x 512], split-K over N ============
// grid (2 Mtiles, 4 Ntiles, 16 Kchunks), block 256 (8 warps, 2x4, warp tile 64x32)
__global__ void __launch_bounds__(256) k_gemmT3(const float* __restrict__ U,
                                                const float* __restrict__ X) {
    __shared__ unsigned Ah[16][PITCH], Al[16][PITCH], Bh[16][PITCH], Bl[16][PITCH];
    int m0 = blockIdx.x * 128;
    int n0 = blockIdx.y * 128;
    int tid = threadIdx.x;
    int w = tid >> 5, lane = tid & 31, g = lane >> 2, t4 = lane & 3;
    int wm = w & 1, wn = w >> 1;
    float C[4][4][4];
#pragma unroll
    for (int i = 0; i < 4; i++)
#pragma unroll
        for (int j = 0; j < 4; j++) { C[i][j][0] = C[i][j][1] = C[i][j][2] = C[i][j][3] = 0.f; }

    for (int kt = 0; kt < 32; kt++) {
        int nbase = blockIdx.z * 512 + kt * 16;
#pragma unroll
        for (int l = 0; l < 8; l++) {
            int idx = tid + 256 * l;
            int r = idx >> 7, m = idx & 127;
            float v = 0.f;
            int gm = m0 + m;
            if (gm < KT) v = U[(nbase + r) * KT + gm];
            unsigned hi = f2tf32(v);
            Ah[r][m] = hi;
            Al[r][m] = f2tf32(v - __uint_as_float(hi));
            float x = X[(nbase + r) * CINC + n0 + m];
            unsigned xh = f2tf32(x);
            Bh[r][m] = xh;
            Bl[r][m] = f2tf32(x - __uint_as_float(xh));
        }
        __syncthreads();
#pragma unroll
        for (int ks = 0; ks < 16; ks += 8) {
            unsigned ah[4][4], al[4][4], bh[4][2], bl[4][2];
#pragma unroll
            for (int mi = 0; mi < 4; mi++) {
                int rm = wm * 64 + mi * 16;
                ah[mi][0] = Ah[ks + t4][rm + g];     ah[mi][1] = Ah[ks + t4][rm + g + 8];
                ah[mi][2] = Ah[ks + t4 + 4][rm + g]; ah[mi][3] = Ah[ks + t4 + 4][rm + g + 8];
                al[mi][0] = Al[ks + t4][rm + g];     al[mi][1] = Al[ks + t4][rm + g + 8];
                al[mi][2] = Al[ks + t4 + 4][rm + g]; al[mi][3] = Al[ks + t4 + 4][rm + g + 8];
            }
#pragma unroll
            for (int ni = 0; ni < 4; ni++) {
                int cn = wn * 32 + ni * 8;
                bh[ni][0] = Bh[ks + t4][cn + g]; bh[ni][1] = Bh[ks + t4 + 4][cn + g];
                bl[ni][0] = Bl[ks + t4][cn + g]; bl[ni][1] = Bl[ks + t4 + 4][cn + g];
            }
#pragma unroll
            for (int mi = 0; mi < 4; mi++)
#pragma unroll
                for (int ni = 0; ni < 4; ni++) {
                    mma_tf32(C[mi][ni], ah[mi], bl[ni]);
                    mma_tf32(C[mi][ni], al[mi], bh[ni]);
                    mma_tf32(C[mi][ni], ah[mi], bh[ni]);
                }
        }
        __syncthreads();
    }
#pragma unroll
    for (int mi = 0; mi < 4; mi++) {
        int r = m0 + wm * 64 + mi * 16 + g;
#pragma unroll
        for (int ni = 0; ni < 4; ni++) {
            int c = n0 + wn * 32 + ni * 8 + 2 * t4;
            if (r < KT) {
                atomicAdd(&d_Tm[r * CINC + c],     C[mi][ni][0]);
                atomicAdd(&d_Tm[r * CINC + c + 1], C[mi][ni][1]);
            }
            if (r + 8 < KT) {
                atomicAdd(&d_Tm[(r + 8) * CINC + c],     C[mi][ni][2]);
                atomicAdd(&d_Tm[(r + 8) * CINC + c + 1], C[mi][ni][3]);
            }
        }
    }
}

// ============ P = T @ Ww  [200 x 256]  (fp32, split-K atomics) ============
// grid (4 Ntiles, 7 Mtiles, 4 Ksplit), block 256
__global__ void __launch_bounds__(256) k_gemmP(const float* __restrict__ Ww) {
    __shared__ float As[32][17];
    __shared__ float Bs[16][64];
    int n0 = blockIdx.x * 64;
    int m0 = blockIdx.y * 32;
    int k0 = blockIdx.z * 128;
    int tid = threadIdx.x;
    int ty = tid >> 6, tx = tid & 63;
    float acc[8] = {};

    for (int kc = 0; kc < 128; kc += 16) {
#pragma unroll
        for (int l = 0; l < 2; l++) {
            int idx = tid + 256 * l;
            int r = idx >> 4, kk = idx & 15;
            As[r][kk] = (m0 + r < KT) ? d_Tm[(m0 + r) * CINC + k0 + kc + kk] : 0.f;
        }
#pragma unroll
        for (int l = 0; l < 4; l++) {
            int idx = tid + 256 * l;
            int kk = idx >> 6, n = idx & 63;
            Bs[kk][n] = Ww[(k0 + kc + kk) * HIDC + n0 + n];
        }
        __syncthreads();
#pragma unroll
        for (int kk = 0; kk < 16; kk++) {
            float b = Bs[kk][tx];
#pragma unroll
            for (int i = 0; i < 8; i++)
                acc[i] = fmaf(As[ty + 4 * i][kk], b, acc[i]);
        }
        __syncthreads();
    }
#pragma unroll
    for (int i = 0; i < 8; i++) {
        int r = m0 + ty + 4 * i;
        if (r < KT) atomicAdd(&d_P[r * HIDC + n0 + tx], acc[i]);
    }
}

// ============ hidden = (U*s) @ P + Wb  [8192 x 256]  (3xtf32, BN stats fused) ============
// grid (64 Mtiles, 2 Ntiles), block 256
__global__ void __launch_bounds__(256) k_gemmH3(const float* __restrict__ U,
                                                const float* __restrict__ Wb,
                                                float* __restrict__ hid) {
    __shared__ unsigned Ah[16][PITCH], Al[16][PITCH], Bh[16][PITCH], Bl[16][PITCH];
    __shared__ float sS[128], sQ[128];
    int m0 = blockIdx.x * 128;
    int n0 = blockIdx.y * 128;
    int tid = threadIdx.x;
    int w = tid >> 5, lane = tid & 31, g = lane >> 2, t4 = lane & 3;
    int wm = w & 1, wn = w >> 1;
    if (tid < 128) { sS[tid] = 0.f; sQ[tid] = 0.f; }
    float C[4][4][4];
#pragma unroll
    for (int i = 0; i < 4; i++)
#pragma unroll
        for (int j = 0; j < 4; j++) { C[i][j][0] = C[i][j][1] = C[i][j][2] = C[i][j][3] = 0.f; }

    for (int kt = 0; kt < 13; kt++) {
        int kbase = kt * 16;
        // A = U * s  transposed into [k][m]
#pragma unroll
        for (int l = 0; l < 8; l++) {
            int idx = tid + 256 * l;
            int m = idx >> 4, kk = idx & 15;
            float v = 0.f;
            if (kbase + kk < KT) v = U[(m0 + m) * KT + kbase + kk] * d_s[kbase + kk];
            unsigned hi = f2tf32(v);
            Ah[kk][m] = hi;
            Al[kk][m] = f2tf32(v - __uint_as_float(hi));
        }
        // B = P[k][n]
#pragma unroll
        for (int l = 0; l < 8; l++) {
            int idx = tid + 256 * l;
            int r = idx >> 7, m = idx & 127;
            float x = (kbase + r < KT) ? d_P[(kbase + r) * HIDC + n0 + m] : 0.f;
            unsigned xh = f2tf32(x);
            Bh[r][m] = xh;
            Bl[r][m] = f2tf32(x - __uint_as_float(xh));
        }
        __syncthreads();
#pragma unroll
        for (int ks = 0; ks < 16; ks += 8) {
            unsigned ah[4][4], al[4][4], bh[4][2], bl[4][2];
#pragma unroll
            for (int mi = 0; mi < 4; mi++) {
                int rm = wm * 64 + mi * 16;
                ah[mi][0] = Ah[ks + t4][rm + g];     ah[mi][1] = Ah[ks + t4][rm + g + 8];
                ah[mi][2] = Ah[ks + t4 + 4][rm + g]; ah[mi][3] = Ah[ks + t4 + 4][rm + g + 8];
                al[mi][0] = Al[ks + t4][rm + g];     al[mi][1] = Al[ks + t4][rm + g + 8];
                al[mi][2] = Al[ks + t4 + 4][rm + g]; al[mi][3] = Al[ks + t4 + 4][rm + g + 8];
            }
#pragma unroll
            for (int ni = 0; ni < 4; ni++) {
                int cn = wn * 32 + ni * 8;
                bh[ni][0] = Bh[ks + t4][cn + g]; bh[ni][1] = Bh[ks + t4 + 4][cn + g];
                bl[ni][0] = Bl[ks + t4][cn + g]; bl[ni][1] = Bl[ks + t4 + 4][cn + g];
            }
#pragma unroll
            for (int mi = 0; mi < 4; mi++)
#pragma unroll
                for (int ni = 0; ni < 4; ni++) {
                    mma_tf32(C[mi][ni], ah[mi], bl[ni]);
                    mma_tf32(C[mi][ni], al[mi], bh[ni]);
                    mma_tf32(C[mi][ni], ah[mi], bh[ni]);
                }
        }
        __syncthreads();
    }
    // epilogue: +Wb, store, BN partial sums
    float ls[8] = {}, lq[8] = {};
#pragma unroll
    for (int mi = 0; mi < 4; mi++) {
        int r = m0 + wm * 64 + mi * 16 + g;
#pragma unroll
        for (int ni = 0; ni < 4; ni++) {
            int c = n0 + wn * 32 + ni * 8 + 2 * t4;
            float b0 = Wb[c], b1 = Wb[c + 1];
            float v0 = C[mi][ni][0] + b0, v1 = C[mi][ni][1] + b1;
            float v2 = C[mi][ni][2] + b0, v3 = C[mi][ni][3] + b1;
            hid[r * HIDC + c] = v0;
            hid[r * HIDC + c + 1] = v1;
            hid[(r + 8) * HIDC + c] = v2;
            hid[(r + 8) * HIDC + c + 1] = v3;
            ls[ni * 2]     += v0 + v2;  lq[ni * 2]     += v0 * v0 + v2 * v2;
            ls[ni * 2 + 1] += v1 + v3;  lq[ni * 2 + 1] += v1 * v1 + v3 * v3;
        }
    }
#pragma unroll
    for (int j = 0; j < 8; j++) {
        float a = ls[j], q = lq[j];
        a += __shfl_xor_sync(0xffffffffu, a, 4);
        a += __shfl_xor_sync(0xffffffffu, a, 8);
        a += __shfl_xor_sync(0xffffffffu, a, 16);
        q += __shfl_xor_sync(0xffffffffu, q, 4);
        q += __shfl_xor_sync(0xffffffffu, q, 8);
        q += __shfl_xor_sync(0xffffffffu, q, 16);
        if (g == 0) {
            int c = wn * 32 + (j >> 1) * 8 + 2 * t4 + (j & 1);
            atomicAdd(&sS[c], a);
            atomicAdd(&sQ[c], q);
        }
    }
    __syncthreads();
    if (tid < 128) {
        atomicAdd(&d_colsum[n0 + tid], sS[tid]);
        atomicAdd(&d_colsq[n0 + tid], sQ[tid]);
    }
}

// ---------------- BN finalize ----------------
__global__ void k_bnfinal() {
    int c = threadIdx.x;
    float m = d_colsum[c] * (1.f / (float)NT);
    float var = d_colsq[c] * (1.f / (float)NT) - m * m;
    d_mu[c] = m;
    d_rsig[c] = rsqrtf(var + 1e-5f);
}

// ---------------- BN-apply + relu + logits + log_softmax ----------------
__global__ void k_head(const float* __restrict__ hid,
                       const float* __restrict__ gamma, const float* __restrict__ beta,
                       const float* __restrict__ Mw, const float* __restrict__ Mb,
                       float* __restrict__ out) {
    __shared__ float hs[HIDC];
    __shared__ float lg[COUTC];
    __shared__ float red[2];
    int n = blockIdx.x;
    for (int c = threadIdx.x; c < HIDC; c += 64) {
        float v = hid[n * HIDC + c];
        v = fmaf((v - d_mu[c]) * d_rsig[c], gamma[c], beta[c]);
        hs[c] = fmaxf(v, 0.f);
    }
    __syncthreads();
    if (threadIdx.x < COUTC) {
        int j = threadIdx.x;
        float a = Mb[j];
#pragma unroll 8
        for (int c = 0; c < HIDC; c++) a = fmaf(hs[c], Mw[c * COUTC + j], a);
        lg[j] = a;
    }
    __syncthreads();
    if (threadIdx.x == 0) {
        float m = lg[0];
        for (int j = 1; j < COUTC; j++) m = fmaxf(m, lg[j]);
        float se = 0.f;
        for (int j = 0; j < COUTC; j++) se += expf(lg[j] - m);
        red[0] = m;
        red[1] = logf(se);
    }
    __syncthreads();
    if (threadIdx.x < COUTC)
        out[n * COUTC + threadIdx.x] = lg[threadIdx.x] - red[0] - red[1];
}

// ---------------- launch ----------------
extern "C" void kernel_launch(void* const* d_in, const int* in_sizes, int n_in,
                              void* d_out, int out_size) {
    const float* X     = (const float*)d_in[0];
    const float* La    = (const float*)d_in[1];
    const float* U     = (const float*)d_in[2];
    const float* eW1   = (const float*)d_in[3];
    const float* eb1   = (const float*)d_in[4];
    const float* eW2   = (const float*)d_in[5];
    const float* eb2   = (const float*)d_in[6];
    const float* eW3   = (const float*)d_in[7];
    const float* eb3   = (const float*)d_in[8];
    const float* gW1   = (const float*)d_in[9];
    const float* gb1   = (const float*)d_in[10];
    const float* gW2   = (const float*)d_in[11];
    const float* gb2   = (const float*)d_in[12];
    const float* Ww    = (const float*)d_in[13];
    const float* Wb    = (const float*)d_in[14];
    const float* gamma = (const float*)d_in[15];
    const float* beta  = (const float*)d_in[16];
    const float* Mw    = (const float*)d_in[17];
    const float* Mb    = (const float*)d_in[18];

    float* out_logits = (float*)d_out;
    float* out_hidden = (float*)d_out + (size_t)NT * COUTC;

    k_zero<<<(KT * CINC + 255) / 256, 256>>>();
    k_table<<<dim3(TGRID / 128, EE), 128>>>(eW1, eb1, eW2, eb2, eW3, eb3);
    k_reduceV<<<NT / 128, 256>>>(U);
    k_gate<<<1, 256>>>(La, gW1, gb1, gW2, gb2);
    k_gemmT3<<<dim3(2, 4, 16), 256>>>(U, X);
    k_gemmP<<<dim3(4, 7, 4), 256>>>(Ww);
    k_gemmH3<<<dim3(64, 2), 256>>>(U, Wb, out_hidden);
    k_bnfinal<<<1, HIDC>>>();
    k_head<<<NT, 64>>>(out_hidden, gamma, beta, Mw, Mb, out_logits);
}

// round 3
// speedup vs baseline: 2.0664x; 1.0671x over previous
#include <cuda_runtime.h>

#define NT    8192
#define KT    200
#define CINC  512
#define HIDC  256
#define COUTC 40
#define EE    5
#define MHD   64
#define TGRID 4096
#define TBL_LO (-8.0f)
#define TBL_HI ( 8.0f)
#define PITCH 136

// ---------------- scratch ----------------
__device__ float d_ftable[EE * TGRID];
__device__ float d_Vsum[KT];
__device__ float d_s[KT];
__device__ float d_Tm[KT * CINC];       // T = U^T X   [200 x 512]
__device__ float d_P[KT * HIDC];        // P = T @ Ww  [200 x 256]
__device__ float d_colsum[HIDC], d_colsq[HIDC], d_mu[HIDC], d_rsig[HIDC];

__device__ __forceinline__ unsigned f2tf32(float x) {
    unsigned r;
    asm("cvt.rna.tf32.f32 %0, %1;" : "=r"(r) : "f"(x));
    return r;
}

__device__ __forceinline__ void mma_tf32(float* c, const unsigned* a, const unsigned* b) {
    asm volatile(
        "mma.sync.aligned.m16n8k8.row.col.f32.tf32.tf32.f32 "
        "{%0,%1,%2,%3},{%4,%5,%6,%7},{%8,%9},{%0,%1,%2,%3};"
        : "+f"(c[0]), "+f"(c[1]), "+f"(c[2]), "+f"(c[3])
        : "r"(a[0]), "r"(a[1]), "r"(a[2]), "r"(a[3]), "r"(b[0]), "r"(b[1]));
}

// ---------------- zero accumulators ----------------
__global__ void k_zero() {
    int i = blockIdx.x * blockDim.x + threadIdx.x;
    if (i < KT * CINC) d_Tm[i] = 0.f;
    if (i < KT * HIDC) d_P[i] = 0.f;
    if (i < KT) d_Vsum[i] = 0.f;
    if (i < HIDC) { d_colsum[i] = 0.f; d_colsq[i] = 0.f; }
}

// ---------------- per-expert PWL tables ----------------
__global__ void k_table(const float* __restrict__ eW1, const float* __restrict__ eb1,
                        const float* __restrict__ eW2, const float* __restrict__ eb2,
                        const float* __restrict__ eW3, const float* __restrict__ eb3) {
    int e = blockIdx.y;
    __shared__ float W2s[MHD * MHD];
    __shared__ float W1s[MHD], b1s[MHD], b2s[MHD], W3s[MHD];
    for (int i = threadIdx.x; i < MHD * MHD; i += blockDim.x) W2s[i] = eW2[e * MHD * MHD + i];
    if (threadIdx.x < MHD) {
        W1s[threadIdx.x] = eW1[e * MHD + threadIdx.x];
        b1s[threadIdx.x] = eb1[e * MHD + threadIdx.x];
        b2s[threadIdx.x] = eb2[e * MHD + threadIdx.x];
        W3s[threadIdx.x] = eW3[e * MHD + threadIdx.x];
    }
    __syncthreads();

    int t = blockIdx.x * blockDim.x + threadIdx.x;
    float x = TBL_LO + (TBL_HI - TBL_LO) * ((float)t / (float)(TGRID - 1));

    float h1[MHD];
#pragma unroll
    for (int h = 0; h < MHD; h++) h1[h] = fmaxf(fmaf(x, W1s[h], b1s[h]), 0.f);

    float v = eb3[e];
    for (int j = 0; j < MHD; j += 4) {
        float a0 = b2s[j], a1 = b2s[j + 1], a2 = b2s[j + 2], a3 = b2s[j + 3];
#pragma unroll
        for (int h = 0; h < MHD; h++) {
            float hv = h1[h];
            float4 w = *(const float4*)&W2s[h * MHD + j];
            a0 = fmaf(hv, w.x, a0);
            a1 = fmaf(hv, w.y, a1);
            a2 = fmaf(hv, w.z, a2);
            a3 = fmaf(hv, w.w, a3);
        }
        v = fmaf(fmaxf(a0, 0.f), W3s[j],     v);
        v = fmaf(fmaxf(a1, 0.f), W3s[j + 1], v);
        v = fmaf(fmaxf(a2, 0.f), W3s[j + 2], v);
        v = fmaf(fmaxf(a3, 0.f), W3s[j + 3], v);
    }
    d_ftable[e * TGRID + t] = v;
}

// ---------------- Vsum[col] = sum_n lerp(f_e, U[n,col]) ----------------
__global__ void k_reduceV(const float* __restrict__ U) {
    int col = threadIdx.x;
    if (col >= KT) return;
    int e = col / 40;
    const float* tbl = d_ftable + e * TGRID;
    const float scale = (float)(TGRID - 1) / (TBL_HI - TBL_LO);
    int n0 = blockIdx.x * 128;

    float sum = 0.f;
    for (int n = n0; n < n0 + 128; n++) {
        float u  = U[n * KT + col];
        float xi = (u - TBL_LO) * scale;
        xi = fminf(fmaxf(xi, 0.f), (float)(TGRID - 2) + 0.9999f);
        int   i  = (int)xi;
        float fr = xi - (float)i;
        float a = tbl[i], b = tbl[i + 1];
        sum += fmaf(fr, b - a, a);
    }
    atomicAdd(&d_Vsum[col], sum);
}

// ---------------- gate + s ----------------
__global__ void k_gate(const float* __restrict__ La,
                       const float* __restrict__ gW1, const float* __restrict__ gb1,
                       const float* __restrict__ gW2, const float* __restrict__ gb2) {
    __shared__ float stats[EE], gsh[EE];
    int tid = threadIdx.x;
    if (tid < EE) {
        float s = 0.f;
        for (int i = 0; i < 40; i++) s += La[tid * 40 + i];
        stats[tid] = s * (1.f / 40.f);
    }
    __syncthreads();
    if (tid == 0) {
        float h[EE], g2[EE];
        for (int j = 0; j < EE; j++) {
            float a = gb1[j];
            for (int i = 0; i < EE; i++) a = fmaf(stats[i], gW1[i * EE + j], a);
            h[j] = fmaxf(a, 0.f);
        }
        for (int j = 0; j < EE; j++) {
            float a = gb2[j];
            for (int i = 0; i < EE; i++) a = fmaf(h[i], gW2[i * EE + j], a);
            g2[j] = a;
        }
        float m = g2[0];
        for (int j = 1; j < EE; j++) m = fmaxf(m, g2[j]);
        float se = 0.f;
        for (int j = 0; j < EE; j++) { g2[j] = expf(g2[j] - m); se += g2[j]; }
        for (int j = 0; j < EE; j++) gsh[j] = g2[j] / se;
    }
    __syncthreads();
    if (tid < KT) d_s[tid] = gsh[tid / 40] * d_Vsum[tid] * (1.f / (float)NT);
}

// ============ 3xtf32 GEMM: T = U^T @ X, split-K over N, reg-prefetch ============
__global__ void __launch_bounds__(256) k_gemmT3(const float* __restrict__ U,
                                                const float* __restrict__ X) {
    __shared__ unsigned Ah[16][PITCH], Al[16][PITCH], Bh[16][PITCH], Bl[16][PITCH];
    int m0 = blockIdx.x * 128;
    int n0 = blockIdx.y * 128;
    int tid = threadIdx.x;
    int w = tid >> 5, lane = tid & 31, g = lane >> 2, t4 = lane & 3;
    int wm = w & 1, wn = w >> 1;
    int lr = tid >> 7, lm = tid & 127;           // load coords: 2 rows / pass
    int gm = m0 + lm;
    bool mok = gm < KT;
    float C[4][4][4];
#pragma unroll
    for (int i = 0; i < 4; i++)
#pragma unroll
        for (int j = 0; j < 4; j++) { C[i][j][0] = C[i][j][1] = C[i][j][2] = C[i][j][3] = 0.f; }

    float uA[8], xA[8], uB[8], xB[8];
    {
        int nbase = blockIdx.z * 512;
#pragma unroll
        for (int l = 0; l < 8; l++) {
            int r = lr + 2 * l;
            uA[l] = mok ? U[(nbase + r) * KT + gm] : 0.f;
            xA[l] = X[(nbase + r) * CINC + n0 + lm];
        }
    }

    for (int kt = 0; kt < 32; kt++) {
#pragma unroll
        for (int l = 0; l < 8; l++) {
            int r = lr + 2 * l;
            unsigned hi = f2tf32(uA[l]);
            Ah[r][lm] = hi;
            Al[r][lm] = f2tf32(uA[l] - __uint_as_float(hi));
            unsigned xh = f2tf32(xA[l]);
            Bh[r][lm] = xh;
            Bl[r][lm] = f2tf32(xA[l] - __uint_as_float(xh));
        }
        __syncthreads();
        if (kt < 31) {
            int nbase = blockIdx.z * 512 + (kt + 1) * 16;
#pragma unroll
            for (int l = 0; l < 8; l++) {
                int r = lr + 2 * l;
                uB[l] = mok ? U[(nbase + r) * KT + gm] : 0.f;
                xB[l] = X[(nbase + r) * CINC + n0 + lm];
            }
        }
#pragma unroll
        for (int ks = 0; ks < 16; ks += 8) {
            unsigned ah[4][4], al[4][4], bh[4][2], bl[4][2];
#pragma unroll
            for (int mi = 0; mi < 4; mi++) {
                int rm = wm * 64 + mi * 16;
                ah[mi][0] = Ah[ks + t4][rm + g];     ah[mi][1] = Ah[ks + t4][rm + g + 8];
                ah[mi][2] = Ah[ks + t4 + 4][rm + g]; ah[mi][3] = Ah[ks + t4 + 4][rm + g + 8];
                al[mi][0] = Al[ks + t4][rm + g];     al[mi][1] = Al[ks + t4][rm + g + 8];
                al[mi][2] = Al[ks + t4 + 4][rm + g]; al[mi][3] = Al[ks + t4 + 4][rm + g + 8];
            }
#pragma unroll
            for (int ni = 0; ni < 4; ni++) {
                int cn = wn * 32 + ni * 8;
                bh[ni][0] = Bh[ks + t4][cn + g]; bh[ni][1] = Bh[ks + t4 + 4][cn + g];
                bl[ni][0] = Bl[ks + t4][cn + g]; bl[ni][1] = Bl[ks + t4 + 4][cn + g];
            }
#pragma unroll
            for (int mi = 0; mi < 4; mi++)
#pragma unroll
                for (int ni = 0; ni < 4; ni++) {
                    mma_tf32(C[mi][ni], ah[mi], bl[ni]);
                    mma_tf32(C[mi][ni], al[mi], bh[ni]);
                    mma_tf32(C[mi][ni], ah[mi], bh[ni]);
                }
        }
        __syncthreads();
#pragma unroll
        for (int l = 0; l < 8; l++) { uA[l] = uB[l]; xA[l] = xB[l]; }
    }
#pragma unroll
    for (int mi = 0; mi < 4; mi++) {
        int r = m0 + wm * 64 + mi * 16 + g;
#pragma unroll
        for (int ni = 0; ni < 4; ni++) {
            int c = n0 + wn * 32 + ni * 8 + 2 * t4;
            if (r < KT) {
                atomicAdd(&d_Tm[r * CINC + c],     C[mi][ni][0]);
                atomicAdd(&d_Tm[r * CINC + c + 1], C[mi][ni][1]);
            }
            if (r + 8 < KT) {
                atomicAdd(&d_Tm[(r + 8) * CINC + c],     C[mi][ni][2]);
                atomicAdd(&d_Tm[(r + 8) * CINC + c + 1], C[mi][ni][3]);
            }
        }
    }
}

// ============ P = T @ Ww  [200 x 256]  (fp32, split-K atomics) ============
__global__ void __launch_bounds__(256) k_gemmP(const float* __restrict__ Ww) {
    __shared__ float As[32][17];
    __shared__ float Bs[16][64];
    int n0 = blockIdx.x * 64;
    int m0 = blockIdx.y * 32;
    int k0 = blockIdx.z * 128;
    int tid = threadIdx.x;
    int ty = tid >> 6, tx = tid & 63;
    float acc[8] = {};

    for (int kc = 0; kc < 128; kc += 16) {
#pragma unroll
        for (int l = 0; l < 2; l++) {
            int idx = tid + 256 * l;
            int r = idx >> 4, kk = idx & 15;
            As[r][kk] = (m0 + r < KT) ? d_Tm[(m0 + r) * CINC + k0 + kc + kk] : 0.f;
        }
#pragma unroll
        for (int l = 0; l < 4; l++) {
            int idx = tid + 256 * l;
            int kk = idx >> 6, n = idx & 63;
            Bs[kk][n] = Ww[(k0 + kc + kk) * HIDC + n0 + n];
        }
        __syncthreads();
#pragma unroll
        for (int kk = 0; kk < 16; kk++) {
            float b = Bs[kk][tx];
#pragma unroll
            for (int i = 0; i < 8; i++)
                acc[i] = fmaf(As[ty + 4 * i][kk], b, acc[i]);
        }
        __syncthreads();
    }
#pragma unroll
    for (int i = 0; i < 8; i++) {
        int r = m0 + ty + 4 * i;
        if (r < KT) atomicAdd(&d_P[r * HIDC + n0 + tx], acc[i]);
    }
}

// ============ hidden = (U*s) @ P + Wb, 3xtf32, BN fused, reg-prefetch ============
__global__ void __launch_bounds__(256) k_gemmH3(const float* __restrict__ U,
                                                const float* __restrict__ Wb,
                                                float* __restrict__ hid) {
    __shared__ unsigned Ah[16][PITCH], Al[16][PITCH], Bh[16][PITCH], Bl[16][PITCH];
    __shared__ float sS[128], sQ[128];
    int m0 = blockIdx.x * 128;
    int n0 = blockIdx.y * 128;
    int tid = threadIdx.x;
    int w = tid >> 5, lane = tid & 31, g = lane >> 2, t4 = lane & 3;
    int wm = w & 1, wn = w >> 1;
    int am = tid >> 4, ak = tid & 15;     // A-load coords (1 elem/pass over 16 passes? no: 8 passes)
    int br = tid >> 7, bm = tid & 127;    // B-load coords
    if (tid < 128) { sS[tid] = 0.f; sQ[tid] = 0.f; }
    float C[4][4][4];
#pragma unroll
    for (int i = 0; i < 4; i++)
#pragma unroll
        for (int j = 0; j < 4; j++) { C[i][j][0] = C[i][j][1] = C[i][j][2] = C[i][j][3] = 0.f; }

    float aA[8], bA[8], aB[8], bB[8];
    {
#pragma unroll
        for (int l = 0; l < 8; l++) {
            int m = am + 16 * l, kk = ak;
            aA[l] = (kk < KT) ? U[(m0 + m) * KT + kk] * d_s[kk] : 0.f;
            int r = br + 2 * l;
            bA[l] = (r < KT) ? d_P[r * HIDC + n0 + bm] : 0.f;
        }
    }

    for (int kt = 0; kt < 13; kt++) {
        int kbase = kt * 16;
#pragma unroll
        for (int l = 0; l < 8; l++) {
            int m = am + 16 * l;
            unsigned hi = f2tf32(aA[l]);
            Ah[ak][m] = hi;
            Al[ak][m] = f2tf32(aA[l] - __uint_as_float(hi));
            int r = br + 2 * l;
            unsigned xh = f2tf32(bA[l]);
            Bh[r][bm] = xh;
            Bl[r][bm] = f2tf32(bA[l] - __uint_as_float(xh));
        }
        __syncthreads();
        if (kt < 12) {
            int kb2 = kbase + 16;
#pragma unroll
            for (int l = 0; l < 8; l++) {
                int m = am + 16 * l, kk = kb2 + ak;
                aB[l] = (kk < KT) ? U[(m0 + m) * KT + kk] * d_s[kk] : 0.f;
                int r = kb2 + br + 2 * l;
                bB[l] = (r < KT) ? d_P[r * HIDC + n0 + bm] : 0.f;
            }
        }
#pragma unroll
        for (int ks = 0; ks < 16; ks += 8) {
            unsigned ah[4][4], al[4][4], bh[4][2], bl[4][2];
#pragma unroll
            for (int mi = 0; mi < 4; mi++) {
                int rm = wm * 64 + mi * 16;
                ah[mi][0] = Ah[ks + t4][rm + g];     ah[mi][1] = Ah[ks + t4][rm + g + 8];
                ah[mi][2] = Ah[ks + t4 + 4][rm + g]; ah[mi][3] = Ah[ks + t4 + 4][rm + g + 8];
                al[mi][0] = Al[ks + t4][rm + g];     al[mi][1] = Al[ks + t4][rm + g + 8];
                al[mi][2] = Al[ks + t4 + 4][rm + g]; al[mi][3] = Al[ks + t4 + 4][rm + g + 8];
            }
#pragma unroll
            for (int ni = 0; ni < 4; ni++) {
                int cn = wn * 32 + ni * 8;
                bh[ni][0] = Bh[ks + t4][cn + g]; bh[ni][1] = Bh[ks + t4 + 4][cn + g];
                bl[ni][0] = Bl[ks + t4][cn + g]; bl[ni][1] = Bl[ks + t4 + 4][cn + g];
            }
#pragma unroll
            for (int mi = 0; mi < 4; mi++)
#pragma unroll
                for (int ni = 0; ni < 4; ni++) {
                    mma_tf32(C[mi][ni], ah[mi], bl[ni]);
                    mma_tf32(C[mi][ni], al[mi], bh[ni]);
                    mma_tf32(C[mi][ni], ah[mi], bh[ni]);
                }
        }
        __syncthreads();
#pragma unroll
        for (int l = 0; l < 8; l++) { aA[l] = aB[l]; bA[l] = bB[l]; }
    }
    // epilogue: +Wb, store, BN partial sums
    float ls[8] = {}, lq[8] = {};
#pragma unroll
    for (int mi = 0; mi < 4; mi++) {
        int r = m0 + wm * 64 + mi * 16 + g;
#pragma unroll
        for (int ni = 0; ni < 4; ni++) {
            int c = n0 + wn * 32 + ni * 8 + 2 * t4;
            float b0 = Wb[c], b1 = Wb[c + 1];
            float v0 = C[mi][ni][0] + b0, v1 = C[mi][ni][1] + b1;
            float v2 = C[mi][ni][2] + b0, v3 = C[mi][ni][3] + b1;
            hid[r * HIDC + c] = v0;
            hid[r * HIDC + c + 1] = v1;
            hid[(r + 8) * HIDC + c] = v2;
            hid[(r + 8) * HIDC + c + 1] = v3;
            ls[ni * 2]     += v0 + v2;  lq[ni * 2]     += v0 * v0 + v2 * v2;
            ls[ni * 2 + 1] += v1 + v3;  lq[ni * 2 + 1] += v1 * v1 + v3 * v3;
        }
    }
#pragma unroll
    for (int j = 0; j < 8; j++) {
        float a = ls[j], q = lq[j];
        a += __shfl_xor_sync(0xffffffffu, a, 4);
        a += __shfl_xor_sync(0xffffffffu, a, 8);
        a += __shfl_xor_sync(0xffffffffu, a, 16);
        q += __shfl_xor_sync(0xffffffffu, q, 4);
        q += __shfl_xor_sync(0xffffffffu, q, 8);
        q += __shfl_xor_sync(0xffffffffu, q, 16);
        if (g == 0) {
            int c = wn * 32 + (j >> 1) * 8 + 2 * t4 + (j & 1);
            atomicAdd(&sS[c], a);
            atomicAdd(&sQ[c], q);
        }
    }
    __syncthreads();
    if (tid < 128) {
        atomicAdd(&d_colsum[n0 + tid], sS[tid]);
        atomicAdd(&d_colsq[n0 + tid], sQ[tid]);
    }
}

// ---------------- BN finalize ----------------
__global__ void k_bnfinal() {
    int c = threadIdx.x;
    float m = d_colsum[c] * (1.f / (float)NT);
    float var = d_colsq[c] * (1.f / (float)NT) - m * m;
    d_mu[c] = m;
    d_rsig[c] = rsqrtf(var + 1e-5f);
}

// ---------------- head: 32 rows/block, Mw cached in smem ----------------
#define HROWS 32
__global__ void __launch_bounds__(256) k_head(const float* __restrict__ hid,
                       const float* __restrict__ gamma, const float* __restrict__ beta,
                       const float* __restrict__ Mw, const float* __restrict__ Mb,
                       float* __restrict__ out) {
    __shared__ float hs[HROWS][HIDC + 4];
    __shared__ float Ms[HIDC * COUTC];
    __shared__ float lg[HROWS][COUTC];
    int tid = threadIdx.x;
    int n0 = blockIdx.x * HROWS;

    // load Mw [256 x 40]
    for (int i = tid; i < HIDC * COUTC; i += 256) Ms[i] = Mw[i];
    // load + BN + relu 32 rows of hidden
    for (int i = tid; i < HROWS * HIDC; i += 256) {
        int r = i >> 8, c = i & 255;
        float v = hid[(n0 + r) * HIDC + c];
        v = fmaf((v - d_mu[c]) * d_rsig[c], gamma[c], beta[c]);
        hs[r][c] = fmaxf(v, 0.f);
    }
    __syncthreads();

    // logits: 1280 outputs over 256 threads (5 each)
#pragma unroll
    for (int l = 0; l < 5; l++) {
        int idx = tid + 256 * l;
        int r = idx / COUTC, j = idx % COUTC;
        float a = Mb[j];
#pragma unroll 8
        for (int c = 0; c < HIDC; c++) a = fmaf(hs[r][c], Ms[c * COUTC + j], a);
        lg[r][j] = a;
    }
    __syncthreads();

    // log_softmax: warp w handles rows 4w..4w+3
    int w = tid >> 5, lane = tid & 31;
#pragma unroll
    for (int rr = 0; rr < 4; rr++) {
        int r = w * 4 + rr;
        float v0 = (lane < COUTC) ? lg[r][lane] : -1e30f;
        float v1 = (lane + 32 < COUTC) ? lg[r][lane + 32] : -1e30f;
        float m = fmaxf(v0, v1);
#pragma unroll
        for (int off = 16; off; off >>= 1) m = fmaxf(m, __shfl_xor_sync(0xffffffffu, m, off));
        float se = 0.f;
        if (lane < COUTC) se += expf(v0 - m);
        if (lane + 32 < COUTC) se += expf(v1 - m);
#pragma unroll
        for (int off = 16; off; off >>= 1) se += __shfl_xor_sync(0xffffffffu, se, off);
        float lse = m + logf(se);
        if (lane < COUTC) out[(n0 + r) * COUTC + lane] = v0 - lse;
        if (lane + 32 < COUTC) out[(n0 + r) * COUTC + lane + 32] = v1 - lse;
    }
}

// ---------------- launch ----------------
extern "C" void kernel_launch(void* const* d_in, const int* in_sizes, int n_in,
                              void* d_out, int out_size) {
    const float* X     = (const float*)d_in[0];
    const float* La    = (const float*)d_in[1];
    const float* U     = (const float*)d_in[2];
    const float* eW1   = (const float*)d_in[3];
    const float* eb1   = (const float*)d_in[4];
    const float* eW2   = (const float*)d_in[5];
    const float* eb2   = (const float*)d_in[6];
    const float* eW3   = (const float*)d_in[7];
    const float* eb3   = (const float*)d_in[8];
    const float* gW1   = (const float*)d_in[9];
    const float* gb1   = (const float*)d_in[10];
    const float* gW2   = (const float*)d_in[11];
    const float* gb2   = (const float*)d_in[12];
    const float* Ww    = (const float*)d_in[13];
    const float* Wb    = (const float*)d_in[14];
    const float* gamma = (const float*)d_in[15];
    const float* beta  = (const float*)d_in[16];
    const float* Mw    = (const float*)d_in[17];
    const float* Mb    = (const float*)d_in[18];

    float* out_logits = (float*)d_out;
    float* out_hidden = (float*)d_out + (size_t)NT * COUTC;

    k_zero<<<(KT * CINC + 255) / 256, 256>>>();
    k_table<<<dim3(TGRID / 128, EE), 128>>>(eW1, eb1, eW2, eb2, eW3, eb3);
    k_reduceV<<<NT / 128, 256>>>(U);
    k_gate<<<1, 256>>>(La, gW1, gb1, gW2, gb2);
    k_gemmT3<<<dim3(2, 4, 16), 256>>>(U, X);
    k_gemmP<<<dim3(4, 7, 4), 256>>>(Ww);
    k_gemmH3<<<dim3(64, 2), 256>>>(U, Wb, out_hidden);
    k_bnfinal<<<1, HIDC>>>();
    k_head<<<NT / HROWS, 256>>>(out_hidden, gamma, beta, Mw, Mb, out_logits);
}

// round 4
// speedup vs baseline: 2.2527x; 1.0901x over previous
#include <cuda_runtime.h>

#define NT    8192
#define KT    200
#define CINC  512
#define HIDC  256
#define COUTC 40
#define EE    5
#define MHD   64
#define TGRID 4096
#define TBL_LO (-8.0f)
#define TBL_HI ( 8.0f)
#define PITCH 136
#define SMEM_GEMM (4 * 2 * 16 * PITCH * 4)   // 4 arrays x 2 stages x 16 x PITCH x 4B = 69632

// ---------------- scratch ----------------
__device__ float d_ftable[EE * TGRID];
__device__ float d_Vsum[KT];
__device__ float d_Tm[KT * CINC];       // T = U^T X   [200 x 512]
__device__ float d_P[KT * HIDC];        // P = T @ Ww  [200 x 256]
__device__ float d_colsum[HIDC], d_colsq[HIDC];

__device__ __forceinline__ unsigned f2tf32(float x) {
    unsigned r;
    asm("cvt.rna.tf32.f32 %0, %1;" : "=r"(r) : "f"(x));
    return r;
}

__device__ __forceinline__ void mma_tf32(float* c, const unsigned* a, const unsigned* b) {
    asm volatile(
        "mma.sync.aligned.m16n8k8.row.col.f32.tf32.tf32.f32 "
        "{%0,%1,%2,%3},{%4,%5,%6,%7},{%8,%9},{%0,%1,%2,%3};"
        : "+f"(c[0]), "+f"(c[1]), "+f"(c[2]), "+f"(c[3])
        : "r"(a[0]), "r"(a[1]), "r"(a[2]), "r"(a[3]), "r"(b[0]), "r"(b[1]));
}

// ---------------- zero accumulators ----------------
__global__ void k_zero() {
    int i = blockIdx.x * blockDim.x + threadIdx.x;
    if (i < KT * CINC) d_Tm[i] = 0.f;
    if (i < KT * HIDC) d_P[i] = 0.f;
    if (i < KT) d_Vsum[i] = 0.f;
    if (i < HIDC) { d_colsum[i] = 0.f; d_colsq[i] = 0.f; }
}

// ---------------- per-expert PWL tables ----------------
__global__ void k_table(const float* __restrict__ eW1, const float* __restrict__ eb1,
                        const float* __restrict__ eW2, const float* __restrict__ eb2,
                        const float* __restrict__ eW3, const float* __restrict__ eb3) {
    int e = blockIdx.y;
    __shared__ float W2s[MHD * MHD];
    __shared__ float W1s[MHD], b1s[MHD], b2s[MHD], W3s[MHD];
    for (int i = threadIdx.x; i < MHD * MHD; i += blockDim.x) W2s[i] = eW2[e * MHD * MHD + i];
    if (threadIdx.x < MHD) {
        W1s[threadIdx.x] = eW1[e * MHD + threadIdx.x];
        b1s[threadIdx.x] = eb1[e * MHD + threadIdx.x];
        b2s[threadIdx.x] = eb2[e * MHD + threadIdx.x];
        W3s[threadIdx.x] = eW3[e * MHD + threadIdx.x];
    }
    __syncthreads();

    int t = blockIdx.x * blockDim.x + threadIdx.x;
    float x = TBL_LO + (TBL_HI - TBL_LO) * ((float)t / (float)(TGRID - 1));

    float h1[MHD];
#pragma unroll
    for (int h = 0; h < MHD; h++) h1[h] = fmaxf(fmaf(x, W1s[h], b1s[h]), 0.f);

    float v = eb3[e];
    for (int j = 0; j < MHD; j += 4) {
        float a0 = b2s[j], a1 = b2s[j + 1], a2 = b2s[j + 2], a3 = b2s[j + 3];
#pragma unroll
        for (int h = 0; h < MHD; h++) {
            float hv = h1[h];
            float4 w = *(const float4*)&W2s[h * MHD + j];
            a0 = fmaf(hv, w.x, a0);
            a1 = fmaf(hv, w.y, a1);
            a2 = fmaf(hv, w.z, a2);
            a3 = fmaf(hv, w.w, a3);
        }
        v = fmaf(fmaxf(a0, 0.f), W3s[j],     v);
        v = fmaf(fmaxf(a1, 0.f), W3s[j + 1], v);
        v = fmaf(fmaxf(a2, 0.f), W3s[j + 2], v);
        v = fmaf(fmaxf(a3, 0.f), W3s[j + 3], v);
    }
    d_ftable[e * TGRID + t] = v;
}

// ---------------- Vsum[col] = sum_n lerp(f_e, U[n,col]) ----------------
__global__ void k_reduceV(const float* __restrict__ U) {
    int col = threadIdx.x;
    if (col >= KT) return;
    int e = col / 40;
    const float* tbl = d_ftable + e * TGRID;
    const float scale = (float)(TGRID - 1) / (TBL_HI - TBL_LO);
    int n0 = blockIdx.x * 64;

    float sum = 0.f;
    for (int n = n0; n < n0 + 64; n++) {
        float u  = U[n * KT + col];
        float xi = (u - TBL_LO) * scale;
        xi = fminf(fmaxf(xi, 0.f), (float)(TGRID - 2) + 0.9999f);
        int   i  = (int)xi;
        float fr = xi - (float)i;
        float a = tbl[i], b = tbl[i + 1];
        sum += fmaf(fr, b - a, a);
    }
    atomicAdd(&d_Vsum[col], sum);
}

// ============ 3xtf32 GEMM: T = U^T @ X, split-K over N, ping-pong smem ============
__global__ void __launch_bounds__(256) k_gemmT3(const float* __restrict__ U,
                                                const float* __restrict__ X) {
    extern __shared__ unsigned smemb[];
    unsigned* AhB = smemb;
    unsigned* AlB = AhB + 2 * 16 * PITCH;
    unsigned* BhB = AlB + 2 * 16 * PITCH;
    unsigned* BlB = BhB + 2 * 16 * PITCH;

    int m0 = blockIdx.x * 128;
    int n0 = blockIdx.y * 128;
    int tid = threadIdx.x;
    int w = tid >> 5, lane = tid & 31, g = lane >> 2, t4 = lane & 3;
    int wm = w & 1, wn = w >> 1;
    int lr = tid >> 7, lm = tid & 127;
    int gm = m0 + lm;
    bool mok = gm < KT;
    float C[4][4][4];
#pragma unroll
    for (int i = 0; i < 4; i++)
#pragma unroll
        for (int j = 0; j < 4; j++) { C[i][j][0] = C[i][j][1] = C[i][j][2] = C[i][j][3] = 0.f; }

    float uA[8], xA[8], uB[8], xB[8];
    {
        int nbase = blockIdx.z * 512;
#pragma unroll
        for (int l = 0; l < 8; l++) {
            int r = lr + 2 * l;
            uA[l] = mok ? U[(nbase + r) * KT + gm] : 0.f;
            xA[l] = X[(nbase + r) * CINC + n0 + lm];
        }
        // store stage 0
#pragma unroll
        for (int l = 0; l < 8; l++) {
            int r = lr + 2 * l;
            unsigned hi = f2tf32(uA[l]);
            AhB[r * PITCH + lm] = hi;
            AlB[r * PITCH + lm] = f2tf32(uA[l] - __uint_as_float(hi));
            unsigned xh = f2tf32(xA[l]);
            BhB[r * PITCH + lm] = xh;
            BlB[r * PITCH + lm] = f2tf32(xA[l] - __uint_as_float(xh));
        }
    }
    __syncthreads();

    for (int kt = 0; kt < 32; kt++) {
        int p = kt & 1;
        const unsigned* AhP = AhB + p * 16 * PITCH;
        const unsigned* AlP = AlB + p * 16 * PITCH;
        const unsigned* BhP = BhB + p * 16 * PITCH;
        const unsigned* BlP = BlB + p * 16 * PITCH;
        if (kt < 31) {
            int nbase = blockIdx.z * 512 + (kt + 1) * 16;
#pragma unroll
            for (int l = 0; l < 8; l++) {
                int r = lr + 2 * l;
                uB[l] = mok ? U[(nbase + r) * KT + gm] : 0.f;
                xB[l] = X[(nbase + r) * CINC + n0 + lm];
            }
        }
#pragma unroll
        for (int ks = 0; ks < 16; ks += 8) {
            unsigned ah[4][4], al[4][4], bh[4][2], bl[4][2];
#pragma unroll
            for (int mi = 0; mi < 4; mi++) {
                int rm = wm * 64 + mi * 16;
                ah[mi][0] = AhP[(ks + t4) * PITCH + rm + g];     ah[mi][1] = AhP[(ks + t4) * PITCH + rm + g + 8];
                ah[mi][2] = AhP[(ks + t4 + 4) * PITCH + rm + g]; ah[mi][3] = AhP[(ks + t4 + 4) * PITCH + rm + g + 8];
                al[mi][0] = AlP[(ks + t4) * PITCH + rm + g];     al[mi][1] = AlP[(ks + t4) * PITCH + rm + g + 8];
                al[mi][2] = AlP[(ks + t4 + 4) * PITCH + rm + g]; al[mi][3] = AlP[(ks + t4 + 4) * PITCH + rm + g + 8];
            }
#pragma unroll
            for (int ni = 0; ni < 4; ni++) {
                int cn = wn * 32 + ni * 8;
                bh[ni][0] = BhP[(ks + t4) * PITCH + cn + g]; bh[ni][1] = BhP[(ks + t4 + 4) * PITCH + cn + g];
                bl[ni][0] = BlP[(ks + t4) * PITCH + cn + g]; bl[ni][1] = BlP[(ks + t4 + 4) * PITCH + cn + g];
            }
#pragma unroll
            for (int mi = 0; mi < 4; mi++)
#pragma unroll
                for (int ni = 0; ni < 4; ni++) {
                    mma_tf32(C[mi][ni], ah[mi], bl[ni]);
                    mma_tf32(C[mi][ni], al[mi], bh[ni]);
                    mma_tf32(C[mi][ni], ah[mi], bh[ni]);
                }
        }
        if (kt < 31) {
            unsigned* AhQ = AhB + (p ^ 1) * 16 * PITCH;
            unsigned* AlQ = AlB + (p ^ 1) * 16 * PITCH;
            unsigned* BhQ = BhB + (p ^ 1) * 16 * PITCH;
            unsigned* BlQ = BlB + (p ^ 1) * 16 * PITCH;
#pragma unroll
            for (int l = 0; l < 8; l++) {
                int r = lr + 2 * l;
                unsigned hi = f2tf32(uB[l]);
                AhQ[r * PITCH + lm] = hi;
                AlQ[r * PITCH + lm] = f2tf32(uB[l] - __uint_as_float(hi));
                unsigned xh = f2tf32(xB[l]);
                BhQ[r * PITCH + lm] = xh;
                BlQ[r * PITCH + lm] = f2tf32(xB[l] - __uint_as_float(xh));
            }
        }
        __syncthreads();
    }
#pragma unroll
    for (int mi = 0; mi < 4; mi++) {
        int r = m0 + wm * 64 + mi * 16 + g;
#pragma unroll
        for (int ni = 0; ni < 4; ni++) {
            int c = n0 + wn * 32 + ni * 8 + 2 * t4;
            if (r < KT) {
                atomicAdd(&d_Tm[r * CINC + c],     C[mi][ni][0]);
                atomicAdd(&d_Tm[r * CINC + c + 1], C[mi][ni][1]);
            }
            if (r + 8 < KT) {
                atomicAdd(&d_Tm[(r + 8) * CINC + c],     C[mi][ni][2]);
                atomicAdd(&d_Tm[(r + 8) * CINC + c + 1], C[mi][ni][3]);
            }
        }
    }
}

// ============ P = T @ Ww  [200 x 256]  (fp32, split-K atomics) ============
__global__ void __launch_bounds__(256) k_gemmP(const float* __restrict__ Ww) {
    __shared__ float As[32][17];
    __shared__ float Bs[16][64];
    int n0 = blockIdx.x * 64;
    int m0 = blockIdx.y * 32;
    int k0 = blockIdx.z * 128;
    int tid = threadIdx.x;
    int ty = tid >> 6, tx = tid & 63;
    float acc[8] = {};

    for (int kc = 0; kc < 128; kc += 16) {
#pragma unroll
        for (int l = 0; l < 2; l++) {
            int idx = tid + 256 * l;
            int r = idx >> 4, kk = idx & 15;
            As[r][kk] = (m0 + r < KT) ? d_Tm[(m0 + r) * CINC + k0 + kc + kk] : 0.f;
        }
#pragma unroll
        for (int l = 0; l < 4; l++) {
            int idx = tid + 256 * l;
            int kk = idx >> 6, n = idx & 63;
            Bs[kk][n] = Ww[(k0 + kc + kk) * HIDC + n0 + n];
        }
        __syncthreads();
#pragma unroll
        for (int kk = 0; kk < 16; kk++) {
            float b = Bs[kk][tx];
#pragma unroll
            for (int i = 0; i < 8; i++)
                acc[i] = fmaf(As[ty + 4 * i][kk], b, acc[i]);
        }
        __syncthreads();
    }
#pragma unroll
    for (int i = 0; i < 8; i++) {
        int r = m0 + ty + 4 * i;
        if (r < KT) atomicAdd(&d_P[r * HIDC + n0 + tx], acc[i]);
    }
}

// ============ hidden = (U*s)@P + Wb, 3xtf32, gate+s fused, BN fused, ping-pong ============
__global__ void __launch_bounds__(256) k_gemmH3(const float* __restrict__ U,
                                                const float* __restrict__ La,
                                                const float* __restrict__ gW1, const float* __restrict__ gb1,
                                                const float* __restrict__ gW2, const float* __restrict__ gb2,
                                                const float* __restrict__ Wb,
                                                float* __restrict__ hid) {
    extern __shared__ unsigned smemb[];
    unsigned* AhB = smemb;
    unsigned* AlB = AhB + 2 * 16 * PITCH;
    unsigned* BhB = AlB + 2 * 16 * PITCH;
    unsigned* BlB = BhB + 2 * 16 * PITCH;
    __shared__ float sS[128], sQ[128];
    __shared__ float s_sm[KT];
    __shared__ float La_sm[KT];
    __shared__ float stats[EE], gsh[EE];

    int m0 = blockIdx.x * 128;
    int n0 = blockIdx.y * 128;
    int tid = threadIdx.x;
    int w = tid >> 5, lane = tid & 31, g = lane >> 2, t4 = lane & 3;
    int wm = w & 1, wn = w >> 1;
    int am = tid >> 4, ak = tid & 15;
    int br = tid >> 7, bm = tid & 127;

    // ---- fused gate: compute s[0..199] into smem ----
    if (tid < 128) { sS[tid] = 0.f; sQ[tid] = 0.f; }
    if (tid < KT) La_sm[tid] = La[tid];
    __syncthreads();
    if (tid < EE) {
        float s = 0.f;
        for (int i = 0; i < 40; i++) s += La_sm[tid * 40 + i];
        stats[tid] = s * (1.f / 40.f);
    }
    __syncthreads();
    if (tid == 0) {
        float h[EE], g2[EE];
        for (int j = 0; j < EE; j++) {
            float a = gb1[j];
            for (int i = 0; i < EE; i++) a = fmaf(stats[i], gW1[i * EE + j], a);
            h[j] = fmaxf(a, 0.f);
        }
        for (int j = 0; j < EE; j++) {
            float a = gb2[j];
            for (int i = 0; i < EE; i++) a = fmaf(h[i], gW2[i * EE + j], a);
            g2[j] = a;
        }
        float m = g2[0];
        for (int j = 1; j < EE; j++) m = fmaxf(m, g2[j]);
        float se = 0.f;
        for (int j = 0; j < EE; j++) { g2[j] = expf(g2[j] - m); se += g2[j]; }
        for (int j = 0; j < EE; j++) gsh[j] = g2[j] / se;
    }
    __syncthreads();
    if (tid < KT) s_sm[tid] = gsh[tid / 40] * d_Vsum[tid] * (1.f / (float)NT);
    __syncthreads();

    float C[4][4][4];
#pragma unroll
    for (int i = 0; i < 4; i++)
#pragma unroll
        for (int j = 0; j < 4; j++) { C[i][j][0] = C[i][j][1] = C[i][j][2] = C[i][j][3] = 0.f; }

    float aA[8], bA[8], aB[8], bB[8];
    {
#pragma unroll
        for (int l = 0; l < 8; l++) {
            int m = am + 16 * l, kk = ak;
            aA[l] = (kk < KT) ? U[(m0 + m) * KT + kk] * s_sm[kk] : 0.f;
            int r = br + 2 * l;
            bA[l] = (r < KT) ? d_P[r * HIDC + n0 + bm] : 0.f;
        }
#pragma unroll
        for (int l = 0; l < 8; l++) {
            int m = am + 16 * l;
            unsigned hi = f2tf32(aA[l]);
            AhB[ak * PITCH + m] = hi;
            AlB[ak * PITCH + m] = f2tf32(aA[l] - __uint_as_float(hi));
            int r = br + 2 * l;
            unsigned xh = f2tf32(bA[l]);
            BhB[r * PITCH + bm] = xh;
            BlB[r * PITCH + bm] = f2tf32(bA[l] - __uint_as_float(xh));
        }
    }
    __syncthreads();

    for (int kt = 0; kt < 13; kt++) {
        int p = kt & 1;
        const unsigned* AhP = AhB + p * 16 * PITCH;
        const unsigned* AlP = AlB + p * 16 * PITCH;
        const unsigned* BhP = BhB + p * 16 * PITCH;
        const unsigned* BlP = BlB + p * 16 * PITCH;
        if (kt < 12) {
            int kb2 = (kt + 1) * 16;
#pragma unroll
            for (int l = 0; l < 8; l++) {
                int m = am + 16 * l, kk = kb2 + ak;
                aB[l] = (kk < KT) ? U[(m0 + m) * KT + kk] * s_sm[kk] : 0.f;
                int r = kb2 + br + 2 * l;
                bB[l] = (r < KT) ? d_P[r * HIDC + n0 + bm] : 0.f;
            }
        }
#pragma unroll
        for (int ks = 0; ks < 16; ks += 8) {
            unsigned ah[4][4], al[4][4], bh[4][2], bl[4][2];
#pragma unroll
            for (int mi = 0; mi < 4; mi++) {
                int rm = wm * 64 + mi * 16;
                ah[mi][0] = AhP[(ks + t4) * PITCH + rm + g];     ah[mi][1] = AhP[(ks + t4) * PITCH + rm + g + 8];
                ah[mi][2] = AhP[(ks + t4 + 4) * PITCH + rm + g]; ah[mi][3] = AhP[(ks + t4 + 4) * PITCH + rm + g + 8];
                al[mi][0] = AlP[(ks + t4) * PITCH + rm + g];     al[mi][1] = AlP[(ks + t4) * PITCH + rm + g + 8];
                al[mi][2] = AlP[(ks + t4 + 4) * PITCH + rm + g]; al[mi][3] = AlP[(ks + t4 + 4) * PITCH + rm + g + 8];
            }
#pragma unroll
            for (int ni = 0; ni < 4; ni++) {
                int cn = wn * 32 + ni * 8;
                bh[ni][0] = BhP[(ks + t4) * PITCH + cn + g]; bh[ni][1] = BhP[(ks + t4 + 4) * PITCH + cn + g];
                bl[ni][0] = BlP[(ks + t4) * PITCH + cn + g]; bl[ni][1] = BlP[(ks + t4 + 4) * PITCH + cn + g];
            }
#pragma unroll
            for (int mi = 0; mi < 4; mi++)
#pragma unroll
                for (int ni = 0; ni < 4; ni++) {
                    mma_tf32(C[mi][ni], ah[mi], bl[ni]);
                    mma_tf32(C[mi][ni], al[mi], bh[ni]);
                    mma_tf32(C[mi][ni], ah[mi], bh[ni]);
                }
        }
        if (kt < 12) {
            unsigned* AhQ = AhB + (p ^ 1) * 16 * PITCH;
            unsigned* AlQ = AlB + (p ^ 1) * 16 * PITCH;
            unsigned* BhQ = BhB + (p ^ 1) * 16 * PITCH;
            unsigned* BlQ = BlB + (p ^ 1) * 16 * PITCH;
#pragma unroll
            for (int l = 0; l < 8; l++) {
                int m = am + 16 * l;
                unsigned hi = f2tf32(aB[l]);
                AhQ[ak * PITCH + m] = hi;
                AlQ[ak * PITCH + m] = f2tf32(aB[l] - __uint_as_float(hi));
                int r = br + 2 * l;
                unsigned xh = f2tf32(bB[l]);
                BhQ[r * PITCH + bm] = xh;
                BlQ[r * PITCH + bm] = f2tf32(bB[l] - __uint_as_float(xh));
            }
        }
        __syncthreads();
    }
    // epilogue: +Wb, store, BN partial sums
    float ls[8] = {}, lq[8] = {};
#pragma unroll
    for (int mi = 0; mi < 4; mi++) {
        int r = m0 + wm * 64 + mi * 16 + g;
#pragma unroll
        for (int ni = 0; ni < 4; ni++) {
            int c = n0 + wn * 32 + ni * 8 + 2 * t4;
            float b0 = Wb[c], b1 = Wb[c + 1];
            float v0 = C[mi][ni][0] + b0, v1 = C[mi][ni][1] + b1;
            float v2 = C[mi][ni][2] + b0, v3 = C[mi][ni][3] + b1;
            hid[r * HIDC + c] = v0;
            hid[r * HIDC + c + 1] = v1;
            hid[(r + 8) * HIDC + c] = v2;
            hid[(r + 8) * HIDC + c + 1] = v3;
            ls[ni * 2]     += v0 + v2;  lq[ni * 2]     += v0 * v0 + v2 * v2;
            ls[ni * 2 + 1] += v1 + v3;  lq[ni * 2 + 1] += v1 * v1 + v3 * v3;
        }
    }
#pragma unroll
    for (int j = 0; j < 8; j++) {
        float a = ls[j], q = lq[j];
        a += __shfl_xor_sync(0xffffffffu, a, 4);
        a += __shfl_xor_sync(0xffffffffu, a, 8);
        a += __shfl_xor_sync(0xffffffffu, a, 16);
        q += __shfl_xor_sync(0xffffffffu, q, 4);
        q += __shfl_xor_sync(0xffffffffu, q, 8);
        q += __shfl_xor_sync(0xffffffffu, q, 16);
        if (g == 0) {
            int c = wn * 32 + (j >> 1) * 8 + 2 * t4 + (j & 1);
            atomicAdd(&sS[c], a);
            atomicAdd(&sQ[c], q);
        }
    }
    __syncthreads();
    if (tid < 128) {
        atomicAdd(&d_colsum[n0 + tid], sS[tid]);
        atomicAdd(&d_colsq[n0 + tid], sQ[tid]);
    }
}

// ---------------- head: BN-finalize fused, 32 rows/block, Mw in smem ----------------
#define HROWS 32
__global__ void __launch_bounds__(256) k_head(const float* __restrict__ hid,
                       const float* __restrict__ gamma, const float* __restrict__ beta,
                       const float* __restrict__ Mw, const float* __restrict__ Mb,
                       float* __restrict__ out) {
    __shared__ float hs[HROWS][HIDC + 4];
    __shared__ float Ms[HIDC * COUTC];
    __shared__ float lg[HROWS][COUTC];
    __shared__ float mu_s[HIDC], rs_s[HIDC];
    int tid = threadIdx.x;
    int n0 = blockIdx.x * HROWS;

    // fused BN finalize
    {
        float m = d_colsum[tid] * (1.f / (float)NT);
        float var = d_colsq[tid] * (1.f / (float)NT) - m * m;
        mu_s[tid] = m;
        rs_s[tid] = rsqrtf(var + 1e-5f);
    }
    for (int i = tid; i < HIDC * COUTC; i += 256) Ms[i] = Mw[i];
    __syncthreads();
    for (int i = tid; i < HROWS * HIDC; i += 256) {
        int r = i >> 8, c = i & 255;
        float v = hid[(n0 + r) * HIDC + c];
        v = fmaf((v - mu_s[c]) * rs_s[c], gamma[c], beta[c]);
        hs[r][c] = fmaxf(v, 0.f);
    }
    __syncthreads();

#pragma unroll
    for (int l = 0; l < 5; l++) {
        int idx = tid + 256 * l;
        int r = idx / COUTC, j = idx % COUTC;
        float a = Mb[j];
#pragma unroll 8
        for (int c = 0; c < HIDC; c++) a = fmaf(hs[r][c], Ms[c * COUTC + j], a);
        lg[r][j] = a;
    }
    __syncthreads();

    int w = tid >> 5, lane = tid & 31;
#pragma unroll
    for (int rr = 0; rr < 4; rr++) {
        int r = w * 4 + rr;
        float v0 = (lane < COUTC) ? lg[r][lane] : -1e30f;
        float v1 = (lane + 32 < COUTC) ? lg[r][lane + 32] : -1e30f;
        float m = fmaxf(v0, v1);
#pragma unroll
        for (int off = 16; off; off >>= 1) m = fmaxf(m, __shfl_xor_sync(0xffffffffu, m, off));
        float se = 0.f;
        if (lane < COUTC) se += expf(v0 - m);
        if (lane + 32 < COUTC) se += expf(v1 - m);
#pragma unroll
        for (int off = 16; off; off >>= 1) se += __shfl_xor_sync(0xffffffffu, se, off);
        float lse = m + logf(se);
        if (lane < COUTC) out[(n0 + r) * COUTC + lane] = v0 - lse;
        if (lane + 32 < COUTC) out[(n0 + r) * COUTC + lane + 32] = v1 - lse;
    }
}

// ---------------- launch ----------------
extern "C" void kernel_launch(void* const* d_in, const int* in_sizes, int n_in,
                              void* d_out, int out_size) {
    const float* X     = (const float*)d_in[0];
    const float* La    = (const float*)d_in[1];
    const float* U     = (const float*)d_in[2];
    const float* eW1   = (const float*)d_in[3];
    const float* eb1   = (const float*)d_in[4];
    const float* eW2   = (const float*)d_in[5];
    const float* eb2   = (const float*)d_in[6];
    const float* eW3   = (const float*)d_in[7];
    const float* eb3   = (const float*)d_in[8];
    const float* gW1   = (const float*)d_in[9];
    const float* gb1   = (const float*)d_in[10];
    const float* gW2   = (const float*)d_in[11];
    const float* gb2   = (const float*)d_in[12];
    const float* Ww    = (const float*)d_in[13];
    const float* Wb    = (const float*)d_in[14];
    const float* gamma = (const float*)d_in[15];
    const float* beta  = (const float*)d_in[16];
    const float* Mw    = (const float*)d_in[17];
    const float* Mb    = (const float*)d_in[18];

    float* out_logits = (float*)d_out;
    float* out_hidden = (float*)d_out + (size_t)NT * COUTC;

    cudaFuncSetAttribute(k_gemmT3, cudaFuncAttributeMaxDynamicSharedMemorySize, SMEM_GEMM);
    cudaFuncSetAttribute(k_gemmH3, cudaFuncAttributeMaxDynamicSharedMemorySize, SMEM_GEMM);

    k_zero<<<(KT * CINC + 255) / 256, 256>>>();
    k_table<<<dim3(TGRID / 128, EE), 128>>>(eW1, eb1, eW2, eb2, eW3, eb3);
    k_reduceV<<<NT / 64, 256>>>(U);
    k_gemmT3<<<dim3(2, 4, 16), 256, SMEM_GEMM>>>(U, X);
    k_gemmP<<<dim3(4, 7, 4), 256>>>(Ww);
    k_gemmH3<<<dim3(64, 2), 256, SMEM_GEMM>>>(U, La, gW1, gb1, gW2, gb2, Wb, out_hidden);
    k_head<<<NT / HROWS, 256>>>(out_hidden, gamma, beta, Mw, Mb, out_logits);
}